// round 11
// baseline (speedup 1.0000x reference)
#include <cuda_runtime.h>
#include <cstdint>
#include <math.h>

#define DD 1024
#define HH 1408
#define NE 8
#define TMAX 4096

// ---------------- scratch (device globals; no allocation allowed) -----------
__device__ int   g_cnt[NE];
__device__ int   g_list[NE * TMAX];
__device__ float g_wgt[NE * TMAX];
__device__ int   g_hix[NE * TMAX];
__device__ float g_h[(size_t)2 * TMAX * HH];   // routed expert hidden (tf32 bits), slot = token*2+k
__device__ float g_hs[(size_t)TMAX * HH];      // shared expert hidden (tf32 bits)

// pre-converted tf32-bit operand buffers
__device__ float g_xt[(size_t)TMAX * DD];
__device__ float g_w1t[(size_t)NE * DD * HH];
__device__ float g_w3t[(size_t)NE * DD * HH];
__device__ float g_w2t[(size_t)NE * HH * DD];
__device__ float g_sw1t[(size_t)DD * HH];
__device__ float g_sw3t[(size_t)DD * HH];
__device__ float g_sw2t[(size_t)HH * DD];

// ---------------- small helpers ---------------------------------------------
__device__ __forceinline__ uint32_t f2tf(float f) {
    uint32_t r;
    asm("cvt.rna.tf32.f32 %0, %1;" : "=r"(r) : "f"(f));
    return r;
}
__device__ __forceinline__ float f2tff(float f) { return __uint_as_float(f2tf(f)); }

__device__ __forceinline__ void mma8(float* c, const uint32_t* a, const uint32_t* b) {
    asm volatile(
        "mma.sync.aligned.m16n8k8.row.col.f32.tf32.tf32.f32 "
        "{%0,%1,%2,%3}, {%4,%5,%6,%7}, {%8,%9}, {%0,%1,%2,%3};"
        : "+f"(c[0]), "+f"(c[1]), "+f"(c[2]), "+f"(c[3])
        : "r"(a[0]), "r"(a[1]), "r"(a[2]), "r"(a[3]), "r"(b[0]), "r"(b[1]));
}

__device__ __forceinline__ void cp16(void* s, const void* g) {
    uint32_t sa = (uint32_t)__cvta_generic_to_shared(s);
    asm volatile("cp.async.cg.shared.global [%0], [%1], 16;" :: "r"(sa), "l"(g));
}
__device__ __forceinline__ void cpcommit() { asm volatile("cp.async.commit_group;" ::: "memory"); }
template <int N>
__device__ __forceinline__ void cpwait() { asm volatile("cp.async.wait_group %0;" :: "n"(N) : "memory"); }

// ---------------- init ------------------------------------------------------
__global__ void init_kernel() {
    if (threadIdx.x < NE) g_cnt[threadIdx.x] = 0;
}

// ---------------- tf32 pre-conversion (RN) ----------------------------------
__global__ void __launch_bounds__(256) conv_kernel(const float4* __restrict__ src,
                                                   float4* __restrict__ dst, int n4) {
    int stride = gridDim.x * blockDim.x;
    for (int i = blockIdx.x * blockDim.x + threadIdx.x; i < n4; i += stride) {
        float4 v = src[i];
        v.x = f2tff(v.x); v.y = f2tff(v.y); v.z = f2tff(v.z); v.w = f2tff(v.w);
        dst[i] = v;
    }
}

// ---------------- gate: softmax + top-2 + routing lists ---------------------
__global__ void gate_kernel(const float* __restrict__ x,
                            const float* __restrict__ gw,
                            const float* __restrict__ gb, int T) {
    int warp = threadIdx.x >> 5, lane = threadIdx.x & 31;
    int t = blockIdx.x * 8 + warp;
    if (t >= T) return;
    const float* xr = x + (size_t)t * DD;
    float acc[NE];
#pragma unroll
    for (int e = 0; e < NE; e++) acc[e] = 0.f;
    for (int i = lane; i < DD; i += 32) {
        float xv = xr[i];
#pragma unroll
        for (int e = 0; e < NE; e++) acc[e] += xv * gw[e * DD + i];
    }
#pragma unroll
    for (int e = 0; e < NE; e++)
#pragma unroll
        for (int o = 16; o > 0; o >>= 1) acc[e] += __shfl_xor_sync(0xffffffffu, acc[e], o);
    if (lane == 0) {
        float m = acc[0];
#pragma unroll
        for (int e = 1; e < NE; e++) m = fmaxf(m, acc[e]);
        float s = 0.f, sc[NE];
#pragma unroll
        for (int e = 0; e < NE; e++) { sc[e] = expf(acc[e] - m); s += sc[e]; }
        float inv = 1.f / s;
#pragma unroll
        for (int e = 0; e < NE; e++) sc[e] *= inv;
        int i0 = 0; float b0 = sc[0] + gb[0];
#pragma unroll
        for (int e = 1; e < NE; e++) { float b = sc[e] + gb[e]; if (b > b0) { b0 = b; i0 = e; } }
        int i1 = -1; float b1v = -1e30f;
#pragma unroll
        for (int e = 0; e < NE; e++) {
            if (e == i0) continue;
            float b = sc[e] + gb[e];
            if (b > b1v) { b1v = b; i1 = e; }
        }
        int p0 = atomicAdd(&g_cnt[i0], 1);
        g_list[i0 * TMAX + p0] = t; g_wgt[i0 * TMAX + p0] = sc[i0]; g_hix[i0 * TMAX + p0] = t * 2;
        int p1 = atomicAdd(&g_cnt[i1], 1);
        g_list[i1 * TMAX + p1] = t; g_wgt[i1 * TMAX + p1] = sc[i1]; g_hix[i1 * TMAX + p1] = t * 2 + 1;
    }
}

// ---------------- FC1: h = silu((x w1 + b1) * (x w3 + b3)) ------------------
// BM=128, BN=64, BK=16, 256 threads (warps 2x4, warp tile 64x16)
// A (xt) and B (w*t) are pre-converted tf32 bit patterns; no cvt in mainloop.
template <bool ROUTED>
__global__ void __launch_bounds__(256) fc1_kernel(
    const float* __restrict__ x,
    const float* __restrict__ W1, const float* __restrict__ B1,
    const float* __restrict__ W3, const float* __restrict__ B3, int T) {
    const int tid = threadIdx.x;
    const int n0 = blockIdx.x * 64;
    const int m0 = blockIdx.y * 128;
    int e = 0, cnt = T;
    if (ROUTED) {
        e = blockIdx.z;
        cnt = g_cnt[e];
        if (m0 >= cnt) return;
        W1 += (size_t)e * DD * HH; W3 += (size_t)e * DD * HH;
        B1 += e * HH; B3 += e * HH;
    } else {
        if (m0 >= T) return;
    }

    __shared__ float As[2][128 * 20];
    __shared__ float Bs1[2][16 * 72];
    __shared__ float Bs3[2][16 * 72];
    __shared__ const float* Aptr[128];
    __shared__ int OutSlot[128];

    if (tid < 128) {
        int r = m0 + tid;
        if (ROUTED) {
            int rr = (r < cnt) ? r : m0;
            Aptr[tid] = x + (size_t)g_list[e * TMAX + rr] * DD;
            OutSlot[tid] = g_hix[e * TMAX + rr];
        } else {
            Aptr[tid] = x + (size_t)r * DD;
            OutSlot[tid] = r;
        }
    }
    __syncthreads();

    auto loadA = [&](int kt, int buf) {
#pragma unroll
        for (int L = 0; L < 2; L++) {
            int idx = tid + L * 256;
            int row = idx >> 2, c4 = idx & 3;
            cp16(&As[buf][row * 20 + c4 * 4], Aptr[row] + kt * 16 + c4 * 4);
        }
    };
    auto loadB = [&](int kt, int buf) {
        int row = tid >> 4, c4 = tid & 15;
        cp16(&Bs1[buf][row * 72 + c4 * 4], W1 + (size_t)(kt * 16 + row) * HH + n0 + c4 * 4);
        cp16(&Bs3[buf][row * 72 + c4 * 4], W3 + (size_t)(kt * 16 + row) * HH + n0 + c4 * 4);
    };

    const int warp = tid >> 5, lane = tid & 31;
    const int wm = warp & 1, wn = warp >> 1;
    const int g = lane >> 2, tg = lane & 3;

    float acc1[4][2][4], acc3[4][2][4];
#pragma unroll
    for (int mt = 0; mt < 4; mt++)
#pragma unroll
        for (int nt = 0; nt < 2; nt++)
#pragma unroll
            for (int i = 0; i < 4; i++) { acc1[mt][nt][i] = 0.f; acc3[mt][nt][i] = 0.f; }

    auto compute = [&](int buf) {
        const uint32_t* ap = (const uint32_t*)As[buf];
        const uint32_t* b1p = (const uint32_t*)Bs1[buf];
        const uint32_t* b3p = (const uint32_t*)Bs3[buf];
#pragma unroll
        for (int s = 0; s < 2; s++) {
            uint32_t af[4][4];
#pragma unroll
            for (int mt = 0; mt < 4; mt++) {
                int r = wm * 64 + mt * 16 + g;
                af[mt][0] = ap[(r) * 20 + s * 8 + tg];
                af[mt][1] = ap[(r + 8) * 20 + s * 8 + tg];
                af[mt][2] = ap[(r) * 20 + s * 8 + tg + 4];
                af[mt][3] = ap[(r + 8) * 20 + s * 8 + tg + 4];
            }
            uint32_t bf1[2][2], bf3[2][2];
#pragma unroll
            for (int nt = 0; nt < 2; nt++) {
                int c = wn * 16 + nt * 8 + g;
                bf1[nt][0] = b1p[(s * 8 + tg) * 72 + c];
                bf1[nt][1] = b1p[(s * 8 + tg + 4) * 72 + c];
                bf3[nt][0] = b3p[(s * 8 + tg) * 72 + c];
                bf3[nt][1] = b3p[(s * 8 + tg + 4) * 72 + c];
            }
#pragma unroll
            for (int mt = 0; mt < 4; mt++)
#pragma unroll
                for (int nt = 0; nt < 2; nt++) {
                    mma8(acc1[mt][nt], af[mt], bf1[nt]);
                    mma8(acc3[mt][nt], af[mt], bf3[nt]);
                }
        }
    };

    loadA(0, 0); loadB(0, 0); cpcommit();
    const int NK = DD / 16;
    for (int kt = 0; kt < NK; kt++) {
        int cur = kt & 1;
        if (kt + 1 < NK) { loadA(kt + 1, cur ^ 1); loadB(kt + 1, cur ^ 1); cpcommit(); cpwait<1>(); }
        else cpwait<0>();
        __syncthreads();
        compute(cur);
        __syncthreads();
    }

#pragma unroll
    for (int nt = 0; nt < 2; nt++) {
        int c = n0 + wn * 16 + nt * 8 + tg * 2;
        float b1a = B1[c], b1b = B1[c + 1], b3a = B3[c], b3b = B3[c + 1];
#pragma unroll
        for (int mt = 0; mt < 4; mt++) {
            int lr0 = wm * 64 + mt * 16 + g;
#pragma unroll
            for (int h = 0; h < 2; h++) {
                int lr = lr0 + h * 8;
                if (m0 + lr >= cnt) continue;
                float* orow = ROUTED ? (g_h + (size_t)OutSlot[lr] * HH)
                                     : (g_hs + (size_t)OutSlot[lr] * HH);
                float v1 = acc1[mt][nt][h * 2 + 0] + b1a;
                float v3 = acc3[mt][nt][h * 2 + 0] + b3a;
                float p = v1 * v3;
                orow[c] = f2tff(p / (1.f + expf(-p)));       // store tf32-rounded
                v1 = acc1[mt][nt][h * 2 + 1] + b1b;
                v3 = acc3[mt][nt][h * 2 + 1] + b3b;
                p = v1 * v3;
                orow[c + 1] = f2tff(p / (1.f + expf(-p)));
            }
        }
    }
}

// ---------------- FC2: out (+)= w * (h w2 + b2) -----------------------------
// BM=128, BN=128, BK=16, 256 threads (warps 2x4, warp tile 64x32)
template <bool ROUTED>
__global__ void __launch_bounds__(256) fc2_kernel(
    const float* __restrict__ W2, const float* __restrict__ B2,
    float* __restrict__ out, int T) {
    const int tid = threadIdx.x;
    const int n0 = blockIdx.x * 128;
    const int m0 = blockIdx.y * 128;
    int e = 0, cnt = T;
    if (ROUTED) {
        e = blockIdx.z;
        cnt = g_cnt[e];
        if (m0 >= cnt) return;
        W2 += (size_t)e * HH * DD;
        B2 += e * DD;
    } else {
        if (m0 >= T) return;
    }

    __shared__ float As[2][128 * 20];
    __shared__ float Bs[2][16 * 136];
    __shared__ const float* Aptr[128];
    __shared__ int Tok[128];
    __shared__ float Wt[128];

    if (tid < 128) {
        int r = m0 + tid;
        if (ROUTED) {
            int rr = (r < cnt) ? r : m0;
            Aptr[tid] = g_h + (size_t)g_hix[e * TMAX + rr] * HH;
            Tok[tid] = g_list[e * TMAX + rr];
            Wt[tid] = g_wgt[e * TMAX + rr];
        } else {
            Aptr[tid] = g_hs + (size_t)r * HH;
            Tok[tid] = r;
            Wt[tid] = 1.f;
        }
    }
    __syncthreads();

    auto loadA = [&](int kt, int buf) {
#pragma unroll
        for (int L = 0; L < 2; L++) {
            int idx = tid + L * 256;
            int row = idx >> 2, c4 = idx & 3;
            cp16(&As[buf][row * 20 + c4 * 4], Aptr[row] + kt * 16 + c4 * 4);
        }
    };
    auto loadB = [&](int kt, int buf) {
#pragma unroll
        for (int L = 0; L < 2; L++) {
            int idx = tid + L * 256;
            int row = idx >> 5, c4 = idx & 31;
            cp16(&Bs[buf][row * 136 + c4 * 4], W2 + (size_t)(kt * 16 + row) * DD + n0 + c4 * 4);
        }
    };

    const int warp = tid >> 5, lane = tid & 31;
    const int wm = warp & 1, wn = warp >> 1;
    const int g = lane >> 2, tg = lane & 3;

    float acc[4][4][4];
#pragma unroll
    for (int mt = 0; mt < 4; mt++)
#pragma unroll
        for (int nt = 0; nt < 4; nt++)
#pragma unroll
            for (int i = 0; i < 4; i++) acc[mt][nt][i] = 0.f;

    auto compute = [&](int buf) {
        const uint32_t* ap = (const uint32_t*)As[buf];
        const uint32_t* bp = (const uint32_t*)Bs[buf];
#pragma unroll
        for (int s = 0; s < 2; s++) {
            uint32_t af[4][4];
#pragma unroll
            for (int mt = 0; mt < 4; mt++) {
                int r = wm * 64 + mt * 16 + g;
                af[mt][0] = ap[(r) * 20 + s * 8 + tg];
                af[mt][1] = ap[(r + 8) * 20 + s * 8 + tg];
                af[mt][2] = ap[(r) * 20 + s * 8 + tg + 4];
                af[mt][3] = ap[(r + 8) * 20 + s * 8 + tg + 4];
            }
            uint32_t bf[4][2];
#pragma unroll
            for (int nt = 0; nt < 4; nt++) {
                int c = wn * 32 + nt * 8 + g;
                bf[nt][0] = bp[(s * 8 + tg) * 136 + c];
                bf[nt][1] = bp[(s * 8 + tg + 4) * 136 + c];
            }
#pragma unroll
            for (int mt = 0; mt < 4; mt++)
#pragma unroll
                for (int nt = 0; nt < 4; nt++) mma8(acc[mt][nt], af[mt], bf[nt]);
        }
    };

    loadA(0, 0); loadB(0, 0); cpcommit();
    const int NK = HH / 16;
    for (int kt = 0; kt < NK; kt++) {
        int cur = kt & 1;
        if (kt + 1 < NK) { loadA(kt + 1, cur ^ 1); loadB(kt + 1, cur ^ 1); cpcommit(); cpwait<1>(); }
        else cpwait<0>();
        __syncthreads();
        compute(cur);
        __syncthreads();
    }

#pragma unroll
    for (int nt = 0; nt < 4; nt++) {
        int c = n0 + wn * 32 + nt * 8 + tg * 2;
        float b2a = B2[c], b2b = B2[c + 1];
#pragma unroll
        for (int mt = 0; mt < 4; mt++) {
            int lr0 = wm * 64 + mt * 16 + g;
#pragma unroll
            for (int h = 0; h < 2; h++) {
                int lr = lr0 + h * 8;
                if (m0 + lr >= cnt) continue;
                float* op = out + (size_t)Tok[lr] * DD + c;
                if (ROUTED) {
                    float w = Wt[lr];
                    atomicAdd(op, w * (acc[mt][nt][h * 2 + 0] + b2a));
                    atomicAdd(op + 1, w * (acc[mt][nt][h * 2 + 1] + b2b));
                } else {
                    op[0] = acc[mt][nt][h * 2 + 0] + b2a;
                    op[1] = acc[mt][nt][h * 2 + 1] + b2b;
                }
            }
        }
    }
}

// ---------------- launch ----------------------------------------------------
extern "C" void kernel_launch(void* const* d_in, const int* in_sizes, int n_in,
                              void* d_out, int out_size) {
    const float* x   = (const float*)d_in[0];
    const float* gw  = (const float*)d_in[1];
    const float* gb  = (const float*)d_in[2];
    const float* w1  = (const float*)d_in[3];
    const float* b1  = (const float*)d_in[4];
    const float* w3  = (const float*)d_in[5];
    const float* b3  = (const float*)d_in[6];
    const float* w2  = (const float*)d_in[7];
    const float* b2  = (const float*)d_in[8];
    const float* sw1 = (const float*)d_in[9];
    const float* sb1 = (const float*)d_in[10];
    const float* sw3 = (const float*)d_in[11];
    const float* sb3 = (const float*)d_in[12];
    const float* sw2 = (const float*)d_in[13];
    const float* sb2 = (const float*)d_in[14];
    float* out = (float*)d_out;

    int T = in_sizes[0] / DD;
    if (T > TMAX) T = TMAX;
    int mTiles = (T + 127) / 128;

    // resolve device-global scratch addresses
    float *xt, *w1t, *w3t, *w2t, *sw1t, *sw3t, *sw2t;
    cudaGetSymbolAddress((void**)&xt,   g_xt);
    cudaGetSymbolAddress((void**)&w1t,  g_w1t);
    cudaGetSymbolAddress((void**)&w3t,  g_w3t);
    cudaGetSymbolAddress((void**)&w2t,  g_w2t);
    cudaGetSymbolAddress((void**)&sw1t, g_sw1t);
    cudaGetSymbolAddress((void**)&sw3t, g_sw3t);
    cudaGetSymbolAddress((void**)&sw2t, g_sw2t);

    init_kernel<<<1, 32>>>();
    gate_kernel<<<(T + 7) / 8, 256>>>(x, gw, gb, T);

    // tf32 pre-conversion (RN) of all GEMM operands
    conv_kernel<<<1184, 256>>>((const float4*)x,   (float4*)xt,   T * DD / 4);
    conv_kernel<<<1184, 256>>>((const float4*)w1,  (float4*)w1t,  NE * DD * HH / 4);
    conv_kernel<<<1184, 256>>>((const float4*)w3,  (float4*)w3t,  NE * DD * HH / 4);
    conv_kernel<<<1184, 256>>>((const float4*)w2,  (float4*)w2t,  NE * HH * DD / 4);
    conv_kernel<<<1184, 256>>>((const float4*)sw1, (float4*)sw1t, DD * HH / 4);
    conv_kernel<<<1184, 256>>>((const float4*)sw3, (float4*)sw3t, DD * HH / 4);
    conv_kernel<<<1184, 256>>>((const float4*)sw2, (float4*)sw2t, HH * DD / 4);

    // routed FC1: grid (H/64, mTiles, E), early-exit beyond per-expert count
    fc1_kernel<true><<<dim3(HH / 64, mTiles, NE), 256>>>(xt, w1t, b1, w3t, b3, T);
    // shared FC1
    fc1_kernel<false><<<dim3(HH / 64, mTiles, 1), 256>>>(xt, sw1t, sb1, sw3t, sb3, T);

    // shared FC2 first: plain stores initialize d_out
    fc2_kernel<false><<<dim3(DD / 128, mTiles, 1), 256>>>(sw2t, sb2, out, T);
    // routed FC2: atomicAdd on top
    fc2_kernel<true><<<dim3(DD / 128, mTiles, NE), 256>>>(w2t, b2, out, T);
}

// round 12
// speedup vs baseline: 1.0843x; 1.0843x over previous
#include <cuda_runtime.h>
#include <cstdint>
#include <math.h>

#define DD 1024
#define HH 1408
#define NE 8
#define TMAX 4096

// ---------------- scratch (device globals; no allocation allowed) -----------
__device__ int   g_cnt[NE];
__device__ int   g_list[NE * TMAX];
__device__ float g_wgt[NE * TMAX];
__device__ int   g_hix[NE * TMAX];
__device__ float g_h[(size_t)2 * TMAX * HH];   // routed hidden (tf32 bits), slot = token*2+k
__device__ float g_hs[(size_t)TMAX * HH];      // shared hidden (tf32 bits)
__device__ float g_xt[(size_t)TMAX * DD];      // x pre-rounded to tf32

// ---------------- small helpers ---------------------------------------------
__device__ __forceinline__ uint32_t f2tf(float f) {
    uint32_t r;
    asm("cvt.rna.tf32.f32 %0, %1;" : "=r"(r) : "f"(f));
    return r;
}
__device__ __forceinline__ float f2tff(float f) { return __uint_as_float(f2tf(f)); }

__device__ __forceinline__ void mma8(float* c, const uint32_t* a, const uint32_t* b) {
    asm volatile(
        "mma.sync.aligned.m16n8k8.row.col.f32.tf32.tf32.f32 "
        "{%0,%1,%2,%3}, {%4,%5,%6,%7}, {%8,%9}, {%0,%1,%2,%3};"
        : "+f"(c[0]), "+f"(c[1]), "+f"(c[2]), "+f"(c[3])
        : "r"(a[0]), "r"(a[1]), "r"(a[2]), "r"(a[3]), "r"(b[0]), "r"(b[1]));
}

__device__ __forceinline__ void cp16(void* s, const void* g) {
    uint32_t sa = (uint32_t)__cvta_generic_to_shared(s);
    asm volatile("cp.async.cg.shared.global [%0], [%1], 16;" :: "r"(sa), "l"(g));
}
__device__ __forceinline__ void cpcommit() { asm volatile("cp.async.commit_group;" ::: "memory"); }
template <int N>
__device__ __forceinline__ void cpwait() { asm volatile("cp.async.wait_group %0;" :: "n"(N) : "memory"); }

// ---------------- init ------------------------------------------------------
__global__ void init_kernel() {
    if (threadIdx.x < NE) g_cnt[threadIdx.x] = 0;
}

// ---------------- tf32 pre-conversion of x (RN) ------------------------------
__global__ void __launch_bounds__(256) convx_kernel(const float4* __restrict__ src,
                                                    float4* __restrict__ dst, int n4) {
    int stride = gridDim.x * blockDim.x;
    for (int i = blockIdx.x * blockDim.x + threadIdx.x; i < n4; i += stride) {
        float4 v = src[i];
        v.x = f2tff(v.x); v.y = f2tff(v.y); v.z = f2tff(v.z); v.w = f2tff(v.w);
        dst[i] = v;
    }
}

// ---------------- gate: softmax + top-2 + routing lists ---------------------
__global__ void gate_kernel(const float* __restrict__ x,
                            const float* __restrict__ gw,
                            const float* __restrict__ gb, int T) {
    int warp = threadIdx.x >> 5, lane = threadIdx.x & 31;
    int t = blockIdx.x * 8 + warp;
    if (t >= T) return;
    const float* xr = x + (size_t)t * DD;
    float acc[NE];
#pragma unroll
    for (int e = 0; e < NE; e++) acc[e] = 0.f;
    for (int i = lane; i < DD; i += 32) {
        float xv = xr[i];
#pragma unroll
        for (int e = 0; e < NE; e++) acc[e] += xv * gw[e * DD + i];
    }
#pragma unroll
    for (int e = 0; e < NE; e++)
#pragma unroll
        for (int o = 16; o > 0; o >>= 1) acc[e] += __shfl_xor_sync(0xffffffffu, acc[e], o);
    if (lane == 0) {
        float m = acc[0];
#pragma unroll
        for (int e = 1; e < NE; e++) m = fmaxf(m, acc[e]);
        float s = 0.f, sc[NE];
#pragma unroll
        for (int e = 0; e < NE; e++) { sc[e] = expf(acc[e] - m); s += sc[e]; }
        float inv = 1.f / s;
#pragma unroll
        for (int e = 0; e < NE; e++) sc[e] *= inv;
        int i0 = 0; float b0 = sc[0] + gb[0];
#pragma unroll
        for (int e = 1; e < NE; e++) { float b = sc[e] + gb[e]; if (b > b0) { b0 = b; i0 = e; } }
        int i1 = -1; float b1v = -1e30f;
#pragma unroll
        for (int e = 0; e < NE; e++) {
            if (e == i0) continue;
            float b = sc[e] + gb[e];
            if (b > b1v) { b1v = b; i1 = e; }
        }
        int p0 = atomicAdd(&g_cnt[i0], 1);
        g_list[i0 * TMAX + p0] = t; g_wgt[i0 * TMAX + p0] = sc[i0]; g_hix[i0 * TMAX + p0] = t * 2;
        int p1 = atomicAdd(&g_cnt[i1], 1);
        g_list[i1 * TMAX + p1] = t; g_wgt[i1 * TMAX + p1] = sc[i1]; g_hix[i1 * TMAX + p1] = t * 2 + 1;
    }
}

// ---------------- FC1 (fused routed + shared): h = silu((x w1+b1)*(x w3+b3))-
// BM=128, BN=64, BK=16, 256 threads (warps 2x4, warp tile 64x16)
// blockIdx.z in [0,NE]: z<NE -> routed expert z; z==NE -> shared expert.
// A (g_xt) is pre-rounded tf32; only B fragments get cvt inline.
__global__ void __launch_bounds__(256) fc1_kernel(
    const float* __restrict__ x,
    const float* __restrict__ W1r, const float* __restrict__ B1r,
    const float* __restrict__ W3r, const float* __restrict__ B3r,
    const float* __restrict__ W1s, const float* __restrict__ B1s,
    const float* __restrict__ W3s, const float* __restrict__ B3s, int T) {
    const int tid = threadIdx.x;
    const int n0 = blockIdx.x * 64;
    const int m0 = blockIdx.y * 128;
    const int e = blockIdx.z;
    const bool SH = (e == NE);
    const float *W1, *B1, *W3, *B3;
    int cnt;
    if (SH) {
        W1 = W1s; B1 = B1s; W3 = W3s; B3 = B3s; cnt = T;
    } else {
        cnt = g_cnt[e];
        W1 = W1r + (size_t)e * DD * HH; W3 = W3r + (size_t)e * DD * HH;
        B1 = B1r + e * HH; B3 = B3r + e * HH;
    }
    if (m0 >= cnt) return;

    __shared__ float As[2][128 * 20];
    __shared__ float Bs1[2][16 * 72];
    __shared__ float Bs3[2][16 * 72];
    __shared__ const float* Aptr[128];
    __shared__ int OutSlot[128];

    if (tid < 128) {
        int r = m0 + tid;
        if (SH) {
            Aptr[tid] = x + (size_t)r * DD;
            OutSlot[tid] = r;
        } else {
            int rr = (r < cnt) ? r : m0;
            Aptr[tid] = x + (size_t)g_list[e * TMAX + rr] * DD;
            OutSlot[tid] = g_hix[e * TMAX + rr];
        }
    }
    __syncthreads();

    auto loadA = [&](int kt, int buf) {
#pragma unroll
        for (int L = 0; L < 2; L++) {
            int idx = tid + L * 256;
            int row = idx >> 2, c4 = idx & 3;
            cp16(&As[buf][row * 20 + c4 * 4], Aptr[row] + kt * 16 + c4 * 4);
        }
    };
    auto loadB = [&](int kt, int buf) {
        int row = tid >> 4, c4 = tid & 15;
        cp16(&Bs1[buf][row * 72 + c4 * 4], W1 + (size_t)(kt * 16 + row) * HH + n0 + c4 * 4);
        cp16(&Bs3[buf][row * 72 + c4 * 4], W3 + (size_t)(kt * 16 + row) * HH + n0 + c4 * 4);
    };

    const int warp = tid >> 5, lane = tid & 31;
    const int wm = warp & 1, wn = warp >> 1;
    const int g = lane >> 2, tg = lane & 3;

    float acc1[4][2][4], acc3[4][2][4];
#pragma unroll
    for (int mt = 0; mt < 4; mt++)
#pragma unroll
        for (int nt = 0; nt < 2; nt++)
#pragma unroll
            for (int i = 0; i < 4; i++) { acc1[mt][nt][i] = 0.f; acc3[mt][nt][i] = 0.f; }

    auto compute = [&](int buf) {
        const uint32_t* ap = (const uint32_t*)As[buf];
#pragma unroll
        for (int s = 0; s < 2; s++) {
            uint32_t af[4][4];
#pragma unroll
            for (int mt = 0; mt < 4; mt++) {
                int r = wm * 64 + mt * 16 + g;
                af[mt][0] = ap[(r) * 20 + s * 8 + tg];
                af[mt][1] = ap[(r + 8) * 20 + s * 8 + tg];
                af[mt][2] = ap[(r) * 20 + s * 8 + tg + 4];
                af[mt][3] = ap[(r + 8) * 20 + s * 8 + tg + 4];
            }
            uint32_t bf1[2][2], bf3[2][2];
#pragma unroll
            for (int nt = 0; nt < 2; nt++) {
                int c = wn * 16 + nt * 8 + g;
                bf1[nt][0] = f2tf(Bs1[buf][(s * 8 + tg) * 72 + c]);
                bf1[nt][1] = f2tf(Bs1[buf][(s * 8 + tg + 4) * 72 + c]);
                bf3[nt][0] = f2tf(Bs3[buf][(s * 8 + tg) * 72 + c]);
                bf3[nt][1] = f2tf(Bs3[buf][(s * 8 + tg + 4) * 72 + c]);
            }
#pragma unroll
            for (int mt = 0; mt < 4; mt++)
#pragma unroll
                for (int nt = 0; nt < 2; nt++) {
                    mma8(acc1[mt][nt], af[mt], bf1[nt]);
                    mma8(acc3[mt][nt], af[mt], bf3[nt]);
                }
        }
    };

    // pipeline: wait -> single sync -> issue next-stage loads -> compute
    loadA(0, 0); loadB(0, 0); cpcommit();
    const int NK = DD / 16;
    for (int kt = 0; kt < NK; kt++) {
        int cur = kt & 1;
        cpwait<0>();
        __syncthreads();
        if (kt + 1 < NK) { loadA(kt + 1, cur ^ 1); loadB(kt + 1, cur ^ 1); cpcommit(); }
        compute(cur);
    }

#pragma unroll
    for (int nt = 0; nt < 2; nt++) {
        int c = n0 + wn * 16 + nt * 8 + tg * 2;
        float b1a = B1[c], b1b = B1[c + 1], b3a = B3[c], b3b = B3[c + 1];
#pragma unroll
        for (int mt = 0; mt < 4; mt++) {
            int lr0 = wm * 64 + mt * 16 + g;
#pragma unroll
            for (int h = 0; h < 2; h++) {
                int lr = lr0 + h * 8;
                if (m0 + lr >= cnt) continue;
                float* orow = SH ? (g_hs + (size_t)OutSlot[lr] * HH)
                                 : (g_h + (size_t)OutSlot[lr] * HH);
                float v1 = acc1[mt][nt][h * 2 + 0] + b1a;
                float v3 = acc3[mt][nt][h * 2 + 0] + b3a;
                float p = v1 * v3;
                orow[c] = f2tff(p / (1.f + expf(-p)));       // store tf32-rounded
                v1 = acc1[mt][nt][h * 2 + 1] + b1b;
                v3 = acc3[mt][nt][h * 2 + 1] + b3b;
                p = v1 * v3;
                orow[c + 1] = f2tff(p / (1.f + expf(-p)));
            }
        }
    }
}

// ---------------- FC2 (fused routed + shared): out += w * (h w2 + b2) -------
// BM=128, BN=128, BK=16, 256 threads (warps 2x4, warp tile 64x32)
// out is zero-initialized; all paths atomicAdd.
__global__ void __launch_bounds__(256) fc2_kernel(
    const float* __restrict__ W2r, const float* __restrict__ B2r,
    const float* __restrict__ W2s, const float* __restrict__ B2s,
    float* __restrict__ out, int T) {
    const int tid = threadIdx.x;
    const int n0 = blockIdx.x * 128;
    const int m0 = blockIdx.y * 128;
    const int e = blockIdx.z;
    const bool SH = (e == NE);
    const float *W2, *B2;
    int cnt;
    if (SH) {
        W2 = W2s; B2 = B2s; cnt = T;
    } else {
        cnt = g_cnt[e];
        W2 = W2r + (size_t)e * HH * DD;
        B2 = B2r + e * DD;
    }
    if (m0 >= cnt) return;

    __shared__ float As[2][128 * 20];
    __shared__ float Bs[2][16 * 136];
    __shared__ const float* Aptr[128];
    __shared__ int Tok[128];
    __shared__ float Wt[128];

    if (tid < 128) {
        int r = m0 + tid;
        if (SH) {
            Aptr[tid] = g_hs + (size_t)r * HH;
            Tok[tid] = r;
            Wt[tid] = 1.f;
        } else {
            int rr = (r < cnt) ? r : m0;
            Aptr[tid] = g_h + (size_t)g_hix[e * TMAX + rr] * HH;
            Tok[tid] = g_list[e * TMAX + rr];
            Wt[tid] = g_wgt[e * TMAX + rr];
        }
    }
    __syncthreads();

    auto loadA = [&](int kt, int buf) {
#pragma unroll
        for (int L = 0; L < 2; L++) {
            int idx = tid + L * 256;
            int row = idx >> 2, c4 = idx & 3;
            cp16(&As[buf][row * 20 + c4 * 4], Aptr[row] + kt * 16 + c4 * 4);
        }
    };
    auto loadB = [&](int kt, int buf) {
#pragma unroll
        for (int L = 0; L < 2; L++) {
            int idx = tid + L * 256;
            int row = idx >> 5, c4 = idx & 31;
            cp16(&Bs[buf][row * 136 + c4 * 4], W2 + (size_t)(kt * 16 + row) * DD + n0 + c4 * 4);
        }
    };

    const int warp = tid >> 5, lane = tid & 31;
    const int wm = warp & 1, wn = warp >> 1;
    const int g = lane >> 2, tg = lane & 3;

    float acc[4][4][4];
#pragma unroll
    for (int mt = 0; mt < 4; mt++)
#pragma unroll
        for (int nt = 0; nt < 4; nt++)
#pragma unroll
            for (int i = 0; i < 4; i++) acc[mt][nt][i] = 0.f;

    auto compute = [&](int buf) {
        const uint32_t* ap = (const uint32_t*)As[buf];
#pragma unroll
        for (int s = 0; s < 2; s++) {
            uint32_t af[4][4];
#pragma unroll
            for (int mt = 0; mt < 4; mt++) {
                int r = wm * 64 + mt * 16 + g;
                af[mt][0] = ap[(r) * 20 + s * 8 + tg];
                af[mt][1] = ap[(r + 8) * 20 + s * 8 + tg];
                af[mt][2] = ap[(r) * 20 + s * 8 + tg + 4];
                af[mt][3] = ap[(r + 8) * 20 + s * 8 + tg + 4];
            }
            uint32_t bf[4][2];
#pragma unroll
            for (int nt = 0; nt < 4; nt++) {
                int c = wn * 32 + nt * 8 + g;
                bf[nt][0] = f2tf(Bs[buf][(s * 8 + tg) * 136 + c]);
                bf[nt][1] = f2tf(Bs[buf][(s * 8 + tg + 4) * 136 + c]);
            }
#pragma unroll
            for (int mt = 0; mt < 4; mt++)
#pragma unroll
                for (int nt = 0; nt < 4; nt++) mma8(acc[mt][nt], af[mt], bf[nt]);
        }
    };

    loadA(0, 0); loadB(0, 0); cpcommit();
    const int NK = HH / 16;
    for (int kt = 0; kt < NK; kt++) {
        int cur = kt & 1;
        cpwait<0>();
        __syncthreads();
        if (kt + 1 < NK) { loadA(kt + 1, cur ^ 1); loadB(kt + 1, cur ^ 1); cpcommit(); }
        compute(cur);
    }

#pragma unroll
    for (int nt = 0; nt < 4; nt++) {
        int c = n0 + wn * 32 + nt * 8 + tg * 2;
        float b2a = B2[c], b2b = B2[c + 1];
#pragma unroll
        for (int mt = 0; mt < 4; mt++) {
            int lr0 = wm * 64 + mt * 16 + g;
#pragma unroll
            for (int h = 0; h < 2; h++) {
                int lr = lr0 + h * 8;
                if (m0 + lr >= cnt) continue;
                float* op = out + (size_t)Tok[lr] * DD + c;
                float w = Wt[lr];
                atomicAdd(op,     w * (acc[mt][nt][h * 2 + 0] + b2a));
                atomicAdd(op + 1, w * (acc[mt][nt][h * 2 + 1] + b2b));
            }
        }
    }
}

// ---------------- launch ----------------------------------------------------
extern "C" void kernel_launch(void* const* d_in, const int* in_sizes, int n_in,
                              void* d_out, int out_size) {
    const float* x   = (const float*)d_in[0];
    const float* gw  = (const float*)d_in[1];
    const float* gb  = (const float*)d_in[2];
    const float* w1  = (const float*)d_in[3];
    const float* b1  = (const float*)d_in[4];
    const float* w3  = (const float*)d_in[5];
    const float* b3  = (const float*)d_in[6];
    const float* w2  = (const float*)d_in[7];
    const float* b2  = (const float*)d_in[8];
    const float* sw1 = (const float*)d_in[9];
    const float* sb1 = (const float*)d_in[10];
    const float* sw3 = (const float*)d_in[11];
    const float* sb3 = (const float*)d_in[12];
    const float* sw2 = (const float*)d_in[13];
    const float* sb2 = (const float*)d_in[14];
    float* out = (float*)d_out;

    int T = in_sizes[0] / DD;
    if (T > TMAX) T = TMAX;
    int mTiles = (T + 127) / 128;

    float* xt;
    cudaGetSymbolAddress((void**)&xt, g_xt);

    init_kernel<<<1, 32>>>();
    gate_kernel<<<(T + 7) / 8, 256>>>(x, gw, gb, T);
    convx_kernel<<<296, 256>>>((const float4*)x, (float4*)xt, T * DD / 4);
    cudaMemsetAsync(out, 0, (size_t)out_size * sizeof(float));

    // fused FC1: z in [0, NE], z==NE is the shared expert
    fc1_kernel<<<dim3(HH / 64, mTiles, NE + 1), 256>>>(
        xt, w1, b1, w3, b3, sw1, sb1, sw3, sb3, T);

    // fused FC2: all paths atomicAdd onto zeroed out
    fc2_kernel<<<dim3(DD / 128, mTiles, NE + 1), 256>>>(
        w2, b2, sw2, sb2, out, T);
}